// round 2
// baseline (speedup 1.0000x reference)
#include <cuda_runtime.h>

// Problem constants
#define NBATCH 64
#define NBINS  256
#define ELEMS_PER_BATCH (256*32*32)      // 262144 floats per batch per tensor
#define F4_PER_BATCH    (ELEMS_PER_BATCH/4)  // 65536 float4
#define CHUNKS 16                         // blocks per (batch, tensor)
#define F4_PER_CHUNK (F4_PER_BATCH/CHUNKS)   // 4096 float4 per block
#define HIST_THREADS 256
#define WARPS_PER_BLOCK (HIST_THREADS/32)

// Scratch (no device allocation allowed): histograms + per-batch KL
__device__ unsigned int g_hist[2][NBATCH][NBINS];
__device__ double       g_kl[NBATCH];

// ---------------------------------------------------------------------------
// Kernel 0: zero the histogram counters
// ---------------------------------------------------------------------------
__global__ void zero_kernel() {
    int idx = blockIdx.x * blockDim.x + threadIdx.x;
    unsigned int* p = &g_hist[0][0][0];
    if (idx < 2 * NBATCH * NBINS) p[idx] = 0u;
}

// ---------------------------------------------------------------------------
// Kernel 1: histogram. grid = (CHUNKS, NBATCH, 2), block = 256.
// Warp-private shared histograms to minimize atomic conflicts, then one
// global atomic per (block, bin).
// ---------------------------------------------------------------------------
__global__ void __launch_bounds__(HIST_THREADS) hist_kernel(
    const float4* __restrict__ feat_s, const float4* __restrict__ feat_t) {

    __shared__ unsigned int sh[WARPS_PER_BLOCK][NBINS];

    // zero shared
    #pragma unroll
    for (int i = threadIdx.x; i < WARPS_PER_BLOCK * NBINS; i += HIST_THREADS)
        (&sh[0][0])[i] = 0u;
    __syncthreads();

    const float4* __restrict__ src = (blockIdx.z == 0) ? feat_s : feat_t;
    const int batch = blockIdx.y;
    const size_t base = (size_t)batch * F4_PER_BATCH + (size_t)blockIdx.x * F4_PER_CHUNK;

    unsigned int* myh = sh[threadIdx.x >> 5];

    #pragma unroll 4
    for (int i = threadIdx.x; i < F4_PER_CHUNK; i += HIST_THREADS) {
        float4 v = src[base + i];
        atomicAdd(&myh[(int)v.x], 1u);
        atomicAdd(&myh[(int)v.y], 1u);
        atomicAdd(&myh[(int)v.z], 1u);
        atomicAdd(&myh[(int)v.w], 1u);
    }
    __syncthreads();

    // reduce warp copies, one global atomic per bin per block
    if (threadIdx.x < NBINS) {
        unsigned int sum = 0;
        #pragma unroll
        for (int w = 0; w < WARPS_PER_BLOCK; w++) sum += sh[w][threadIdx.x];
        atomicAdd(&g_hist[blockIdx.z][batch][threadIdx.x], sum);
    }
}

// ---------------------------------------------------------------------------
// Kernel 2: per-batch KL. 64 blocks x 256 threads (one thread per bin).
// fp64 for the tiny reduction (16K elements total) — deterministic trees.
//
// x = log(count + 1e-8) / T  with T = 4  ->  exp(x) = (count+eps)^0.25,
// which is <= 22.6, so logsumexp needs no max-subtraction.
// ---------------------------------------------------------------------------
__global__ void __launch_bounds__(NBINS) kl_kernel() {
    const int n = blockIdx.x;
    const int b = threadIdx.x;

    double xs = log((double)g_hist[0][n][b] + 1e-8) * 0.25;  // /T
    double xt = log((double)g_hist[1][n][b] + 1e-8) * 0.25;
    double es = exp(xs);
    double et = exp(xt);

    __shared__ double rs[NBINS];
    __shared__ double rt[NBINS];
    rs[b] = es; rt[b] = et;
    __syncthreads();
    #pragma unroll
    for (int s = NBINS / 2; s > 0; s >>= 1) {
        if (b < s) { rs[b] += rs[b + s]; rt[b] += rt[b + s]; }
        __syncthreads();
    }
    double Ss = rs[0];
    double St = rt[0];
    __syncthreads();

    double lse_s = log(Ss);
    double lse_t = log(St);
    double pt = et / St;                              // softmax target
    double term = pt * ((xt - lse_t) - (xs - lse_s)); // p_t*(log p_t - log_softmax_s)

    rs[b] = term;
    __syncthreads();
    #pragma unroll
    for (int s = NBINS / 2; s > 0; s >>= 1) {
        if (b < s) rs[b] += rs[b + s];
        __syncthreads();
    }
    if (b == 0) g_kl[n] = rs[0];
}

// ---------------------------------------------------------------------------
// Kernel 3: final deterministic sum over batches, scale by T^2 / N.
// ---------------------------------------------------------------------------
__global__ void final_kernel(float* __restrict__ out) {
    __shared__ double red[NBATCH];
    int t = threadIdx.x;
    red[t] = g_kl[t];
    __syncthreads();
    #pragma unroll
    for (int s = NBATCH / 2; s > 0; s >>= 1) {
        if (t < s) red[t] += red[t + s];
        __syncthreads();
    }
    if (t == 0) out[0] = (float)(red[0] * (4.0 * 4.0) / (double)NBATCH);
}

// ---------------------------------------------------------------------------
extern "C" void kernel_launch(void* const* d_in, const int* in_sizes, int n_in,
                              void* d_out, int out_size) {
    const float4* feat_s = (const float4*)d_in[0];
    const float4* feat_t = (const float4*)d_in[1];
    float* out = (float*)d_out;

    (void)in_sizes; (void)n_in; (void)out_size;

    zero_kernel<<<(2 * NBATCH * NBINS + 255) / 256, 256>>>();

    dim3 grid(CHUNKS, NBATCH, 2);
    hist_kernel<<<grid, HIST_THREADS>>>(feat_s, feat_t);

    kl_kernel<<<NBATCH, NBINS>>>();

    final_kernel<<<1, NBATCH>>>(out);
}

// round 3
// speedup vs baseline: 1.0056x; 1.0056x over previous
#include <cuda_runtime.h>

// Problem constants
#define NBATCH 64
#define NBINS  256
#define ELEMS_PER_BATCH (256*32*32)          // 262144 floats per batch per tensor
#define F4_PER_BATCH    (ELEMS_PER_BATCH/4)  // 65536 float4
#define CHUNKS 2                             // blocks per (batch, tensor)
#define F4_PER_CHUNK (F4_PER_BATCH/CHUNKS)   // 32768 float4 per block
#define HIST_THREADS 512
#define WARPS_PER_BLOCK (HIST_THREADS/32)    // 16

// Scratch (no device allocation allowed).
// Partial histograms are STORED (not accumulated) -> no zeroing kernel needed.
__device__ unsigned int g_part[2][NBATCH][CHUNKS][NBINS];
__device__ double       g_kl[NBATCH];
__device__ unsigned int g_ctr;               // last-block ticket; reset by last block

// ---------------------------------------------------------------------------
// Kernel 1: histogram. grid = (CHUNKS, NBATCH, 2), block = 512 (256 blocks).
// Warp-private shared histograms; per-block partial written with plain stores.
// ---------------------------------------------------------------------------
__global__ void __launch_bounds__(HIST_THREADS) hist_kernel(
    const float4* __restrict__ feat_s, const float4* __restrict__ feat_t) {

    __shared__ unsigned int sh[WARPS_PER_BLOCK][NBINS];

    #pragma unroll
    for (int i = threadIdx.x; i < WARPS_PER_BLOCK * NBINS; i += HIST_THREADS)
        (&sh[0][0])[i] = 0u;
    __syncthreads();

    const float4* __restrict__ src = (blockIdx.z == 0) ? feat_s : feat_t;
    const size_t base = (size_t)blockIdx.y * F4_PER_BATCH
                      + (size_t)blockIdx.x * F4_PER_CHUNK;

    unsigned int* myh = sh[threadIdx.x >> 5];

    #pragma unroll 8
    for (int i = threadIdx.x; i < F4_PER_CHUNK; i += HIST_THREADS) {
        float4 v = src[base + i];
        atomicAdd(&myh[(int)v.x], 1u);
        atomicAdd(&myh[(int)v.y], 1u);
        atomicAdd(&myh[(int)v.z], 1u);
        atomicAdd(&myh[(int)v.w], 1u);
    }
    __syncthreads();

    // reduce warp copies; plain store of the partial (overwrites old replay)
    if (threadIdx.x < NBINS) {
        unsigned int sum = 0;
        #pragma unroll
        for (int w = 0; w < WARPS_PER_BLOCK; w++) sum += sh[w][threadIdx.x];
        g_part[blockIdx.z][blockIdx.y][blockIdx.x][threadIdx.x] = sum;
    }
}

// ---------------------------------------------------------------------------
// Kernel 2: per-batch KL + fused final reduction (last-block ticket).
// 64 blocks x 256 threads (one thread per bin). fp64 for the tiny math.
//
// x = log(count + 1e-8) / T, T = 4 -> exp(x) = (count+eps)^0.25 <= 22.6,
// so logsumexp needs no max-subtraction.
// ---------------------------------------------------------------------------
__global__ void __launch_bounds__(NBINS) kl_final_kernel(float* __restrict__ out) {
    const int n = blockIdx.x;
    const int b = threadIdx.x;

    unsigned int cs = 0, ct = 0;
    #pragma unroll
    for (int c = 0; c < CHUNKS; c++) {
        cs += g_part[0][n][c][b];
        ct += g_part[1][n][c][b];
    }

    double xs = log((double)cs + 1e-8) * 0.25;  // /T
    double xt = log((double)ct + 1e-8) * 0.25;
    double es = exp(xs);
    double et = exp(xt);

    __shared__ double rs[NBINS];
    __shared__ double rt[NBINS];
    rs[b] = es; rt[b] = et;
    __syncthreads();
    #pragma unroll
    for (int s = NBINS / 2; s > 0; s >>= 1) {
        if (b < s) { rs[b] += rs[b + s]; rt[b] += rt[b + s]; }
        __syncthreads();
    }
    double Ss = rs[0];
    double St = rt[0];
    __syncthreads();

    double lse_s = log(Ss);
    double lse_t = log(St);
    double pt = et / St;                              // softmax target
    double term = pt * ((xt - lse_t) - (xs - lse_s)); // p_t*(log p_t - log_softmax_s)

    rs[b] = term;
    __syncthreads();
    #pragma unroll
    for (int s = NBINS / 2; s > 0; s >>= 1) {
        if (b < s) rs[b] += rs[b + s];
        __syncthreads();
    }

    // publish per-batch KL, then take a ticket
    __shared__ unsigned int s_ticket;
    if (b == 0) {
        g_kl[n] = rs[0];
        __threadfence();
        s_ticket = atomicAdd(&g_ctr, 1u);
    }
    __syncthreads();

    // last block performs the deterministic final sum and resets the ticket
    if (s_ticket == NBATCH - 1) {
        __threadfence();
        __shared__ double red[NBATCH];
        if (b < NBATCH) red[b] = *((volatile double*)&g_kl[b]);
        __syncthreads();
        #pragma unroll
        for (int s = NBATCH / 2; s > 0; s >>= 1) {
            if (b < s) red[b] += red[b + s];
            __syncthreads();
        }
        if (b == 0) {
            out[0] = (float)(red[0] * (4.0 * 4.0) / (double)NBATCH);
            g_ctr = 0;   // ready for next graph replay
        }
    }
}

// ---------------------------------------------------------------------------
extern "C" void kernel_launch(void* const* d_in, const int* in_sizes, int n_in,
                              void* d_out, int out_size) {
    const float4* feat_s = (const float4*)d_in[0];
    const float4* feat_t = (const float4*)d_in[1];
    float* out = (float*)d_out;

    (void)in_sizes; (void)n_in; (void)out_size;

    dim3 grid(CHUNKS, NBATCH, 2);
    hist_kernel<<<grid, HIST_THREADS>>>(feat_s, feat_t);

    kl_final_kernel<<<NBATCH, NBINS>>>(out);
}

// round 4
// speedup vs baseline: 1.4744x; 1.4662x over previous
#include <cuda_runtime.h>

// Problem constants
#define NBATCH 64
#define NBINS  256
#define ELEMS_PER_BATCH (256*32*32)          // 262144 floats per batch per tensor
#define F4_PER_BATCH    (ELEMS_PER_BATCH/4)  // 65536 float4
#define CHUNKS 4                             // blocks per (batch, tensor)
#define F4_PER_CHUNK (F4_PER_BATCH/CHUNKS)   // 16384 float4 per block
#define HIST_THREADS 512
#define WARPS_PER_BLOCK (HIST_THREADS/32)    // 16

// Scratch (no device allocation allowed).
// Partial histograms are STORED (not accumulated) -> no zeroing kernel needed.
__device__ unsigned int g_part[2][NBATCH][CHUNKS][NBINS];
__device__ float        g_kl[NBATCH];
__device__ unsigned int g_ctr;               // last-block ticket; reset by last block

// ---------------------------------------------------------------------------
// Kernel 1: histogram. grid = (CHUNKS, NBATCH, 2), block = 512 (512 blocks).
// Warp-private shared histograms; per-block partial written with plain stores.
// ---------------------------------------------------------------------------
__global__ void __launch_bounds__(HIST_THREADS) hist_kernel(
    const float4* __restrict__ feat_s, const float4* __restrict__ feat_t) {

    __shared__ unsigned int sh[WARPS_PER_BLOCK][NBINS];

    #pragma unroll
    for (int i = threadIdx.x; i < WARPS_PER_BLOCK * NBINS; i += HIST_THREADS)
        (&sh[0][0])[i] = 0u;
    __syncthreads();

    const float4* __restrict__ src = (blockIdx.z == 0) ? feat_s : feat_t;
    const size_t base = (size_t)blockIdx.y * F4_PER_BATCH
                      + (size_t)blockIdx.x * F4_PER_CHUNK;

    unsigned int* myh = sh[threadIdx.x >> 5];

    #pragma unroll 8
    for (int i = threadIdx.x; i < F4_PER_CHUNK; i += HIST_THREADS) {
        float4 v = src[base + i];
        atomicAdd(&myh[(int)v.x], 1u);
        atomicAdd(&myh[(int)v.y], 1u);
        atomicAdd(&myh[(int)v.z], 1u);
        atomicAdd(&myh[(int)v.w], 1u);
    }
    __syncthreads();

    // reduce warp copies; plain store of the partial (overwrites old replay)
    if (threadIdx.x < NBINS) {
        unsigned int sum = 0;
        #pragma unroll
        for (int w = 0; w < WARPS_PER_BLOCK; w++) sum += sh[w][threadIdx.x];
        g_part[blockIdx.z][blockIdx.y][blockIdx.x][threadIdx.x] = sum;
    }
}

// ---------------------------------------------------------------------------
// Kernel 2: per-batch KL + fused final reduction (last-block ticket).
// 64 blocks x 256 threads (one thread per bin). All fp32, restructured to
// avoid cancellation:
//   e = (c + eps)^(1/T) = sqrt(sqrt(c + eps))           (T = 4)
//   log-prob difference = 0.25*log(a_t/a_s) - log(S_t/S_s)
// Logs of RATIOS keep absolute error ~1 ulp where the naive form cancels.
// ---------------------------------------------------------------------------
__global__ void __launch_bounds__(NBINS) kl_final_kernel(float* __restrict__ out) {
    const int n = blockIdx.x;
    const int b = threadIdx.x;

    unsigned int cs = 0, ct = 0;
    #pragma unroll
    for (int c = 0; c < CHUNKS; c++) {
        cs += g_part[0][n][c][b];
        ct += g_part[1][n][c][b];
    }

    float as_ = (float)cs + 1e-8f;   // exact for cs>=1; 1e-8 for cs==0
    float at_ = (float)ct + 1e-8f;
    float es = sqrtf(sqrtf(as_));    // (a)^(1/4) = exp(log(a)/T), T=4
    float et = sqrtf(sqrtf(at_));

    __shared__ float rs[NBINS];
    __shared__ float rt[NBINS];
    rs[b] = es; rt[b] = et;
    __syncthreads();
    #pragma unroll
    for (int s = NBINS / 2; s > 0; s >>= 1) {
        if (b < s) { rs[b] += rs[b + s]; rt[b] += rt[b + s]; }
        __syncthreads();
    }
    float Ss = rs[0];
    float St = rt[0];
    __syncthreads();

    float log_ratio_S = logf(St / Ss);           // lse_t - lse_s
    float pt = et / St;                          // softmax target prob
    float diff = 0.25f * logf(at_ / as_) - log_ratio_S;  // log p_t - log p_s
    float term = pt * diff;

    rs[b] = term;
    __syncthreads();
    #pragma unroll
    for (int s = NBINS / 2; s > 0; s >>= 1) {
        if (b < s) rs[b] += rs[b + s];
        __syncthreads();
    }

    // publish per-batch KL, then take a ticket
    __shared__ unsigned int s_ticket;
    if (b == 0) {
        g_kl[n] = rs[0];
        __threadfence();
        s_ticket = atomicAdd(&g_ctr, 1u);
    }
    __syncthreads();

    // last block performs the deterministic final sum and resets the ticket
    if (s_ticket == NBATCH - 1) {
        __threadfence();
        __shared__ float red[NBATCH];
        if (b < NBATCH) red[b] = *((volatile float*)&g_kl[b]);
        __syncthreads();
        #pragma unroll
        for (int s = NBATCH / 2; s > 0; s >>= 1) {
            if (b < s) red[b] += red[b + s];
            __syncthreads();
        }
        if (b == 0) {
            out[0] = red[0] * (16.0f / (float)NBATCH);  // * T^2 / N
            g_ctr = 0;   // ready for next graph replay
        }
    }
}

// ---------------------------------------------------------------------------
extern "C" void kernel_launch(void* const* d_in, const int* in_sizes, int n_in,
                              void* d_out, int out_size) {
    const float4* feat_s = (const float4*)d_in[0];
    const float4* feat_t = (const float4*)d_in[1];
    float* out = (float*)d_out;

    (void)in_sizes; (void)n_in; (void)out_size;

    dim3 grid(CHUNKS, NBATCH, 2);
    hist_kernel<<<grid, HIST_THREADS>>>(feat_s, feat_t);

    kl_final_kernel<<<NBATCH, NBINS>>>(out);
}